// round 16
// baseline (speedup 1.0000x reference)
#include <cuda_runtime.h>

// MovingNCA, comms-field formulation (R16):
//  The 9 planes P_ij collapse into ONE field A(n,m) = sum_ij P_ij(n+i,m+j)
//  (the comms value itself). Each cell reads a = comms_b + Aold[pos] (sole
//  reader), zeroes Aold[pos] (making it the pre-zeroed buffer for step t+2),
//  and scatter-adds its 9 contributions acc[q] into Anew at the 3x3
//  neighborhood via REDG (center carries aold forward: Anew = Aold + delta).
//  Plane mem ops 27 -> 11 per cell; plane footprint 19 MB -> 2 MB.
//  Channels: all 96 via tanh.approx folded affine (R15); class -> REDG.v4
//  scratch (R13); action ch keep exact ex2+rcp path (bit-stable decisions).

#define N_NEO 510
#define G     512
#define NCELLS (N_NEO * N_NEO)
#define ASTRIDE 512
#define NCA_THRESH 0.0007f
#define NLOG2E (-1.4426950408889634f)

__device__ float   g_A[2][ASTRIDE * N_NEO];  // ping-pong comms field
__device__ float4  g_cls4[8][NCELLS];        // class accumulators
__device__ ushort2 g_perc[NCELLS];           // perception positions
__device__ float   g_K[9];                   // K_q = sum_c 0.5*comms_w[q][c]

__global__ void nca_init(const float* __restrict__ comms_w) {
    long stride = (long)gridDim.x * blockDim.x;
    long tid = (long)blockIdx.x * blockDim.x + threadIdx.x;
    float* A = &g_A[0][0];
    for (long i = tid; i < 2L * ASTRIDE * N_NEO; i += stride) A[i] = 0.0f;
    float* c = &g_cls4[0][0].x;
    for (long i = tid; i < 32L * NCELLS; i += stride) c[i] = 0.0f;
    for (long i = tid; i < NCELLS; i += stride)
        g_perc[i] = make_ushort2((unsigned short)(i / N_NEO),
                                 (unsigned short)(i % N_NEO));
    if (tid < 9) {
        float k = 0.0f;
        for (int cc = 0; cc < 96; cc++)
            k += 0.5f * comms_w[tid * 96 + cc];
        g_K[tid] = k;
    }
}

__global__ void nca_final(float* __restrict__ out) {
    int cell = blockIdx.x * 256 + threadIdx.x;
    if (cell >= NCELLS) return;
    float* op = out + (size_t)cell * 32;
#pragma unroll
    for (int j = 0; j < 8; j++)
        *reinterpret_cast<float4*>(op + 4 * j) = g_cls4[j][cell];
}

// exact sigmoid; weights prescaled by -log2(e): x = -log2(e)*z
__device__ __forceinline__ float sigmoid_pre(float x) {
    float e;
    asm("ex2.approx.f32 %0, %1;" : "=f"(e) : "f"(x));
    float r;
    asm("rcp.approx.f32 %0, %1;" : "=f"(r) : "f"(1.0f + e));
    return r;
}

__device__ __forceinline__ float tanh_apx(float x) {
    float r;
    asm("tanh.approx.f32 %0, %1;" : "=f"(r) : "f"(x));
    return r;
}

__device__ __forceinline__ void red_add_f(float* p, float v) {
    asm volatile("red.global.add.f32 [%0], %1;"
                 :: "l"(p), "f"(v) : "memory");
}

__device__ __forceinline__ void red_add_v4(float* p, float s0, float s1,
                                           float s2, float s3) {
    asm volatile("red.global.add.v4.f32 [%0], {%1, %2, %3, %4};"
                 :: "l"(p), "f"(s0), "f"(s1), "f"(s2), "f"(s3) : "memory");
}

__global__ __launch_bounds__(256, 4) void nca_step(
    const float* __restrict__ img,
    const float* __restrict__ comms_w,
    const float* __restrict__ comms_b,
    const float* __restrict__ perc_w,
    const float* __restrict__ perc_b,
    const float* __restrict__ out_w,
    const float* __restrict__ out_b,
    int parity)
{
    __shared__ __align__(16) float scw[9 * 96];   // 0.5*comms_w, all channels
    __shared__ __align__(16) float su[100], sv[100], sob[100];  // prescaled
    __shared__ float spw[9], sK[9];
    __shared__ float sbias[2];                    // [0]=perc_b [1]=comms_b

    int t = threadIdx.y * 32 + threadIdx.x;
    for (int i = t; i < 864; i += 256) scw[i] = 0.5f * comms_w[i];
    if (t < 98) {
        float sc = (t < 96) ? 0.5f : NLOG2E;   // tanh half-arg vs ex2 prescale
        su[t]  = sc * out_w[t];
        sv[t]  = sc * out_w[98 + t];
        sob[t] = sc * out_b[t];
    }
    else if (t < 107) spw[t - 98] = perc_w[t - 98];
    else if (t == 107) sbias[0] = perc_b[0];
    else if (t == 108) sbias[1] = comms_b[0];
    else if (t >= 128 && t < 137) sK[t - 128] = g_K[t - 128];
    __syncthreads();

    int n = blockIdx.y * 8 + threadIdx.y;
    if (n >= N_NEO) return;
    int m0 = blockIdx.x * 64 + threadIdx.x;

    float* __restrict__ Aold = &g_A[parity][0];
    float* __restrict__ Anew = &g_A[parity ^ 1][0];

    bool valid[2];
    int  cellc[2];            // clamped cell index (safe reads)
    float a[2], araw[2], b[2];
    ushort2 pp[2];

#pragma unroll
    for (int u = 0; u < 2; u++) {
        int mm = m0 + 32 * u;
        valid[u] = (mm < N_NEO);
        int mc = mm < N_NEO ? mm : (N_NEO - 1);
        cellc[u] = n * N_NEO + mc;

        // comms: single read of accumulated field; zero for reuse at t+2
        int apos = n * ASTRIDE + mc;
        float av = Aold[apos];
        if (valid[u]) Aold[apos] = 0.0f;
        araw[u] = av;
        a[u] = av + sbias[1];

        // perception: 3x3 img patch at perc position
        ushort2 p = g_perc[cellc[u]];
        pp[u] = p;
        float bv = sbias[0];
#pragma unroll
        for (int q = 0; q < 9; q++) {
            int i = q / 3, j = q % 3;
            bv = fmaf(img[(p.x + i) * G + (p.y + j)], spw[q], bv);
        }
        b[u] = bv;
    }

    float acc[2][9];
#pragma unroll
    for (int u = 0; u < 2; u++)
#pragma unroll
        for (int q = 0; q < 9; q++) acc[u][q] = sK[q];

    // ---- hidden channels 0..63 : tanh path, folded affine ----
#pragma unroll 4
    for (int c4 = 0; c4 < 64; c4 += 4) {
        float4 u4 = *reinterpret_cast<const float4*>(&su[c4]);
        float4 v4 = *reinterpret_cast<const float4*>(&sv[c4]);
        float4 o4 = *reinterpret_cast<const float4*>(&sob[c4]);
        float s[2][4];
#pragma unroll
        for (int u = 0; u < 2; u++) {
            s[u][0] = tanh_apx(fmaf(a[u], u4.x, fmaf(b[u], v4.x, o4.x)));
            s[u][1] = tanh_apx(fmaf(a[u], u4.y, fmaf(b[u], v4.y, o4.y)));
            s[u][2] = tanh_apx(fmaf(a[u], u4.z, fmaf(b[u], v4.z, o4.z)));
            s[u][3] = tanh_apx(fmaf(a[u], u4.w, fmaf(b[u], v4.w, o4.w)));
        }
#pragma unroll
        for (int q = 0; q < 9; q++) {
            float4 w4 = *reinterpret_cast<const float4*>(&scw[q * 96 + c4]);
#pragma unroll
            for (int u = 0; u < 2; u++)
                acc[u][q] = fmaf(w4.x, s[u][0], fmaf(w4.y, s[u][1],
                            fmaf(w4.z, s[u][2], fmaf(w4.w, s[u][3], acc[u][q]))));
        }
    }

    // ---- class channels 64..95 : tanh path + REDG (s = 0.5 + 0.5 t) ----
#pragma unroll 2
    for (int c4 = 64; c4 < 96; c4 += 4) {
        float4 u4 = *reinterpret_cast<const float4*>(&su[c4]);
        float4 v4 = *reinterpret_cast<const float4*>(&sv[c4]);
        float4 o4 = *reinterpret_cast<const float4*>(&sob[c4]);
        float s[2][4];
#pragma unroll
        for (int u = 0; u < 2; u++) {
            s[u][0] = tanh_apx(fmaf(a[u], u4.x, fmaf(b[u], v4.x, o4.x)));
            s[u][1] = tanh_apx(fmaf(a[u], u4.y, fmaf(b[u], v4.y, o4.y)));
            s[u][2] = tanh_apx(fmaf(a[u], u4.z, fmaf(b[u], v4.z, o4.z)));
            s[u][3] = tanh_apx(fmaf(a[u], u4.w, fmaf(b[u], v4.w, o4.w)));
        }
        int j4 = (c4 - 64) >> 2;
#pragma unroll
        for (int u = 0; u < 2; u++) {
            if (valid[u])
                red_add_v4(&g_cls4[j4][cellc[u]].x,
                           fmaf(0.5f, s[u][0], 0.5f),
                           fmaf(0.5f, s[u][1], 0.5f),
                           fmaf(0.5f, s[u][2], 0.5f),
                           fmaf(0.5f, s[u][3], 0.5f));
        }
#pragma unroll
        for (int q = 0; q < 9; q++) {
            float4 w4 = *reinterpret_cast<const float4*>(&scw[q * 96 + c4]);
#pragma unroll
            for (int u = 0; u < 2; u++)
                acc[u][q] = fmaf(w4.x, s[u][0], fmaf(w4.y, s[u][1],
                            fmaf(w4.z, s[u][2], fmaf(w4.w, s[u][3], acc[u][q]))));
        }
    }

    // ---- scatter comms contributions + action/perc update ----
    float u96 = su[96], v96 = sv[96], o96 = sob[96];
    float u97 = su[97], v97 = sv[97], o97 = sob[97];
#pragma unroll
    for (int u = 0; u < 2; u++) {
        if (!valid[u]) continue;
        int mm = m0 + 32 * u;

        // scatter acc[q] to Anew(n+1-i, mm+1-j); center carries Aold forward
#pragma unroll
        for (int q = 0; q < 9; q++) {
            int i = q / 3, j = q % 3;
            int tn = n + 1 - i;
            int tm = mm + 1 - j;
            float v = (q == 4) ? (acc[u][4] + araw[u]) : acc[u][q];
            if (tn >= 0 && tn < N_NEO && tm >= 0 && tm < N_NEO)
                red_add_f(&Anew[tn * ASTRIDE + tm], v);
        }

        float s0 = sigmoid_pre(fmaf(a[u], u96, fmaf(b[u], v96, o96)));
        float s1 = sigmoid_pre(fmaf(a[u], u97, fmaf(b[u], v97, o97)));
        int dx = (s0 > NCA_THRESH) ? 1 : ((s0 < -NCA_THRESH) ? -1 : 0);
        int dy = (s1 > NCA_THRESH) ? 1 : ((s1 < -NCA_THRESH) ? -1 : 0);
        int px = min(max((int)pp[u].x + dx, 0), N_NEO - 1);
        int py = min(max((int)pp[u].y + dy, 0), N_NEO - 1);
        g_perc[cellc[u]] = make_ushort2((unsigned short)px, (unsigned short)py);
    }
}

extern "C" void kernel_launch(void* const* d_in, const int* in_sizes, int n_in,
                              void* d_out, int out_size) {
    const float* img     = (const float*)d_in[0];
    const float* comms_w = (const float*)d_in[1];
    const float* comms_b = (const float*)d_in[2];
    const float* perc_w  = (const float*)d_in[3];
    const float* perc_b  = (const float*)d_in[4];
    const float* out_w   = (const float*)d_in[5];
    const float* out_b   = (const float*)d_in[6];
    float* out = (float*)d_out;

    nca_init<<<1024, 256>>>(comms_w);

    dim3 bs(32, 8);
    dim3 gs((N_NEO + 63) / 64, (N_NEO + 7) / 8);   // 8 x 64 = 512 blocks
    for (int t = 0; t < 50; t++)
        nca_step<<<gs, bs>>>(img, comms_w, comms_b, perc_w, perc_b,
                             out_w, out_b, t & 1);

    nca_final<<<(NCELLS + 255) / 256, 256>>>(out);
}

// round 17
// speedup vs baseline: 1.0523x; 1.0523x over previous
#include <cuda_runtime.h>

// MovingNCA, plane-reduced formulation (R17 = R15 + 2 micro-cuts):
//  state(96ch) -> 9 planes P_ij = <state, comms_w[i,j,:]>.
//  comms a = b_c + sum_ij P_ij(n+i,m+j); percep b = 3x3 img gather at perc pos.
//  All 96 channels via tanh.approx folded affine: sigma = 0.5 + 0.5 tanh(z/2),
//  planes += (0.5w)*t with K_q = sum_c 0.5 w_qc; class ch -> REDG.v4 scratch.
//  R17a: acc[u][q] initialized to hOld[center] + K_q -> center loads issue
//        BEFORE the channel loops (latency covered by FMA work); tail = pure STG.
//  R17b: action decisions via logit threshold (sigma monotone, always > 0):
//        s > TH  <=>  x < log2(1/TH - 1) = 10.479372 in the prescaled var;
//        the "< -TH" branch can never fire. No MUFU in the decision path.

#define N_NEO 510
#define G     512
#define G2    (G * G)
#define NCELLS (N_NEO * N_NEO)
#define NLOG2E (-1.4426950408889634f)
#define XTH    10.479372f            // log2(1/0.0007 - 1)

__device__ float   g_h[2][9][G2];        // ping-pong comms planes
__device__ float4  g_cls4[8][NCELLS];    // class accumulators, 4 ch per float4
__device__ ushort2 g_perc[NCELLS];       // perception positions
__device__ float   g_K[9];               // K_q = sum_{c<96} 0.5*comms_w[q][c]

__global__ void nca_init(const float* __restrict__ comms_w) {
    long stride = (long)gridDim.x * blockDim.x;
    long tid = (long)blockIdx.x * blockDim.x + threadIdx.x;
    float* h = &g_h[0][0][0];
    for (long i = tid; i < 2L * 9 * G2; i += stride) h[i] = 0.0f;
    float* c = &g_cls4[0][0].x;
    for (long i = tid; i < 32L * NCELLS; i += stride) c[i] = 0.0f;
    for (long i = tid; i < NCELLS; i += stride)
        g_perc[i] = make_ushort2((unsigned short)(i / N_NEO),
                                 (unsigned short)(i % N_NEO));
    if (tid < 9) {
        float k = 0.0f;
        for (int cc = 0; cc < 96; cc++)
            k += 0.5f * comms_w[tid * 96 + cc];
        g_K[tid] = k;
    }
}

__global__ void nca_final(float* __restrict__ out) {
    int cell = blockIdx.x * 256 + threadIdx.x;
    if (cell >= NCELLS) return;
    float* op = out + (size_t)cell * 32;
#pragma unroll
    for (int j = 0; j < 8; j++)
        *reinterpret_cast<float4*>(op + 4 * j) = g_cls4[j][cell];
}

__device__ __forceinline__ float tanh_apx(float x) {
    float r;
    asm("tanh.approx.f32 %0, %1;" : "=f"(r) : "f"(x));
    return r;
}

__device__ __forceinline__ void red_add_v4(float* p, float s0, float s1,
                                           float s2, float s3) {
    asm volatile("red.global.add.v4.f32 [%0], {%1, %2, %3, %4};"
                 :: "l"(p), "f"(s0), "f"(s1), "f"(s2), "f"(s3) : "memory");
}

__global__ __launch_bounds__(256, 4) void nca_step(
    const float* __restrict__ img,
    const float* __restrict__ comms_w,
    const float* __restrict__ comms_b,
    const float* __restrict__ perc_w,
    const float* __restrict__ perc_b,
    const float* __restrict__ out_w,
    const float* __restrict__ out_b,
    int parity)
{
    __shared__ __align__(16) float scw[9 * 96];   // 0.5*comms_w, all channels
    __shared__ __align__(16) float su[100], sv[100], sob[100];  // prescaled
    __shared__ float spw[9], sK[9];
    __shared__ float sbias[2];                    // [0]=perc_b [1]=comms_b

    int t = threadIdx.y * 32 + threadIdx.x;
    for (int i = t; i < 864; i += 256) scw[i] = 0.5f * comms_w[i];
    if (t < 98) {
        float sc = (t < 96) ? 0.5f : NLOG2E;   // tanh half-arg vs ex2 prescale
        su[t]  = sc * out_w[t];
        sv[t]  = sc * out_w[98 + t];
        sob[t] = sc * out_b[t];
    }
    else if (t < 107) spw[t - 98] = perc_w[t - 98];
    else if (t == 107) sbias[0] = perc_b[0];
    else if (t == 108) sbias[1] = comms_b[0];
    else if (t >= 128 && t < 137) sK[t - 128] = g_K[t - 128];
    __syncthreads();

    int n = blockIdx.y * 8 + threadIdx.y;
    if (n >= N_NEO) return;
    int m0 = blockIdx.x * 64 + threadIdx.x;

    const float* __restrict__ hOld = &g_h[parity][0][0];
    float* __restrict__ hNew = &g_h[parity ^ 1][0][0];

    bool valid[2];
    int  cellc[2];            // clamped cell index (safe reads)
    int  hcx[2];              // plane write/center index
    float a[2], b[2];
    ushort2 pp[2];
    float acc[2][9];

#pragma unroll
    for (int u = 0; u < 2; u++) {
        int mm = m0 + 32 * u;
        valid[u] = (mm < N_NEO);
        int mc = mm < N_NEO ? mm : (N_NEO - 1);
        cellc[u] = n * N_NEO + mc;
        hcx[u] = (n + 1) * G + (mc + 1);

        // center loads hoisted: acc starts at hOld[center] + K_q so the
        // 9 LDGs issue before the channel loops (latency covered by FMAs)
#pragma unroll
        for (int q = 0; q < 9; q++)
            acc[u][q] = hOld[q * G2 + hcx[u]] + sK[q];

        // comms gather over 9 planes
        float av = sbias[1];
#pragma unroll
        for (int q = 0; q < 9; q++) {
            int i = q / 3, j = q % 3;
            av += hOld[q * G2 + (n + i) * G + (mc + j)];
        }
        a[u] = av;

        // perception: 3x3 img patch at perc position
        ushort2 p = g_perc[cellc[u]];
        pp[u] = p;
        float bv = sbias[0];
#pragma unroll
        for (int q = 0; q < 9; q++) {
            int i = q / 3, j = q % 3;
            bv = fmaf(img[(p.x + i) * G + (p.y + j)], spw[q], bv);
        }
        b[u] = bv;
    }

    // ---- hidden channels 0..63 : tanh path, folded affine ----
#pragma unroll 4
    for (int c4 = 0; c4 < 64; c4 += 4) {
        float4 u4 = *reinterpret_cast<const float4*>(&su[c4]);
        float4 v4 = *reinterpret_cast<const float4*>(&sv[c4]);
        float4 o4 = *reinterpret_cast<const float4*>(&sob[c4]);
        float s[2][4];
#pragma unroll
        for (int u = 0; u < 2; u++) {
            s[u][0] = tanh_apx(fmaf(a[u], u4.x, fmaf(b[u], v4.x, o4.x)));
            s[u][1] = tanh_apx(fmaf(a[u], u4.y, fmaf(b[u], v4.y, o4.y)));
            s[u][2] = tanh_apx(fmaf(a[u], u4.z, fmaf(b[u], v4.z, o4.z)));
            s[u][3] = tanh_apx(fmaf(a[u], u4.w, fmaf(b[u], v4.w, o4.w)));
        }
#pragma unroll
        for (int q = 0; q < 9; q++) {
            float4 w4 = *reinterpret_cast<const float4*>(&scw[q * 96 + c4]);
#pragma unroll
            for (int u = 0; u < 2; u++)
                acc[u][q] = fmaf(w4.x, s[u][0], fmaf(w4.y, s[u][1],
                            fmaf(w4.z, s[u][2], fmaf(w4.w, s[u][3], acc[u][q]))));
        }
    }

    // ---- class channels 64..95 : tanh path + REDG (s = 0.5 + 0.5 t) ----
#pragma unroll 2
    for (int c4 = 64; c4 < 96; c4 += 4) {
        float4 u4 = *reinterpret_cast<const float4*>(&su[c4]);
        float4 v4 = *reinterpret_cast<const float4*>(&sv[c4]);
        float4 o4 = *reinterpret_cast<const float4*>(&sob[c4]);
        float s[2][4];
#pragma unroll
        for (int u = 0; u < 2; u++) {
            s[u][0] = tanh_apx(fmaf(a[u], u4.x, fmaf(b[u], v4.x, o4.x)));
            s[u][1] = tanh_apx(fmaf(a[u], u4.y, fmaf(b[u], v4.y, o4.y)));
            s[u][2] = tanh_apx(fmaf(a[u], u4.z, fmaf(b[u], v4.z, o4.z)));
            s[u][3] = tanh_apx(fmaf(a[u], u4.w, fmaf(b[u], v4.w, o4.w)));
        }
        int j4 = (c4 - 64) >> 2;
#pragma unroll
        for (int u = 0; u < 2; u++) {
            if (valid[u])
                red_add_v4(&g_cls4[j4][cellc[u]].x,
                           fmaf(0.5f, s[u][0], 0.5f),
                           fmaf(0.5f, s[u][1], 0.5f),
                           fmaf(0.5f, s[u][2], 0.5f),
                           fmaf(0.5f, s[u][3], 0.5f));
        }
#pragma unroll
        for (int q = 0; q < 9; q++) {
            float4 w4 = *reinterpret_cast<const float4*>(&scw[q * 96 + c4]);
#pragma unroll
            for (int u = 0; u < 2; u++)
                acc[u][q] = fmaf(w4.x, s[u][0], fmaf(w4.y, s[u][1],
                            fmaf(w4.z, s[u][2], fmaf(w4.w, s[u][3], acc[u][q]))));
        }
    }

    // ---- plane writes (pure STG) + threshold action/perc update ----
    float u96 = su[96], v96 = sv[96], o96 = sob[96];
    float u97 = su[97], v97 = sv[97], o97 = sob[97];
#pragma unroll
    for (int u = 0; u < 2; u++) {
        if (!valid[u]) continue;
#pragma unroll
        for (int q = 0; q < 9; q++)
            hNew[q * G2 + hcx[u]] = acc[u][q];

        // x = -log2(e) * z; sigma(z) > TH  <=>  x < XTH. sigma > 0 > -TH always.
        float x0 = fmaf(a[u], u96, fmaf(b[u], v96, o96));
        float x1 = fmaf(a[u], u97, fmaf(b[u], v97, o97));
        int dx = (x0 < XTH) ? 1 : 0;
        int dy = (x1 < XTH) ? 1 : 0;
        int px = min((int)pp[u].x + dx, N_NEO - 1);
        int py = min((int)pp[u].y + dy, N_NEO - 1);
        g_perc[cellc[u]] = make_ushort2((unsigned short)px, (unsigned short)py);
    }
}

extern "C" void kernel_launch(void* const* d_in, const int* in_sizes, int n_in,
                              void* d_out, int out_size) {
    const float* img     = (const float*)d_in[0];
    const float* comms_w = (const float*)d_in[1];
    const float* comms_b = (const float*)d_in[2];
    const float* perc_w  = (const float*)d_in[3];
    const float* perc_b  = (const float*)d_in[4];
    const float* out_w   = (const float*)d_in[5];
    const float* out_b   = (const float*)d_in[6];
    float* out = (float*)d_out;

    nca_init<<<1024, 256>>>(comms_w);

    dim3 bs(32, 8);
    dim3 gs((N_NEO + 63) / 64, (N_NEO + 7) / 8);   // 8 x 64 = 512 blocks
    for (int t = 0; t < 50; t++)
        nca_step<<<gs, bs>>>(img, comms_w, comms_b, perc_w, perc_b,
                             out_w, out_b, t & 1);

    nca_final<<<(NCELLS + 255) / 256, 256>>>(out);
}